// round 9
// baseline (speedup 1.0000x reference)
#include <cuda_runtime.h>
#include <cuda_bf16.h>
#include <math.h>
#include <cstdint>

// ---------------- problem constants ----------------
constexpr int BATCH = 64;
constexpr int IMG   = 224;
constexpr int PCH   = 16;
constexpr int SHIFT = 8;
constexpr int GRD   = 14;
constexpr int NPAT  = 196;
constexpr int NT    = 197;
constexpr int DIM   = 384;
constexpr int DEPTH = 12;
constexpr int NH    = 12;
constexpr int DHD   = 32;
constexpr int INNER = 384;
constexpr int TRI   = 1152;
constexpr int MLPD  = 1536;
constexpr int NCLS  = 1000;
constexpr int PD    = 1792;
constexpr float LNEPS = 1e-5f;

constexpr int MROWS = BATCH * NT;            // 12608
constexpr int MPAD  = 12672;                 // 99 * 128
constexpr int MPE   = BATCH * NPAT;          // 12544 = 98 * 128

// ---------------- attention smem layout ----------------
constexpr int KT_STRIDE = 225;
constexpr int VT_STRIDE = 228;
constexpr int ATTN_KT_FLOATS = DHD * KT_STRIDE;
constexpr int ATTN_VT_FLOATS = DHD * VT_STRIDE;
constexpr int ATTN_PW_FLOATS = 8 * 4 * 224;
constexpr int ATTN_SMEM_BYTES = (ATTN_KT_FLOATS + ATTN_VT_FLOATS + ATTN_PW_FLOATS) * 4;

// ---------------- GEMM tile config ----------------
// Per stage: bufA 128 rows x 128B (hi bytes [0,64) | lo bytes [64,128)), SW128-swizzled;
//            bufW same at +16KB.  Stage = 32KB, 3 stages = 96KB -> 2 CTAs/SM.
constexpr int BK        = 32;
constexpr int TILE128   = 16384;
constexpr int STAGE_B   = 2 * TILE128;        // 32768
constexpr int STAGES    = 3;
constexpr int GEMM_SMEM = STAGES * STAGE_B;   // 98304

#define SWZ(o) ((o) ^ ((((o) >> 7) & 7) << 4))

// ---------------- device scratch ----------------
__device__ float g_mean [BATCH * IMG * IMG];
__device__ float g_emb  [(size_t)MPE * DIM];
__device__ float g_x    [(size_t)MPAD * DIM];
__device__ float g_qkv  [(size_t)MPAD * TRI];
__device__ float g_cls  [BATCH * DIM];

__device__ __align__(16) __nv_bfloat16 g_act1_hi[(size_t)MPE * PD];
__device__ __align__(16) __nv_bfloat16 g_act1_lo[(size_t)MPE * PD];
__device__ __align__(16) __nv_bfloat16 g_act2_hi[(size_t)MPAD * MLPD];
__device__ __align__(16) __nv_bfloat16 g_act2_lo[(size_t)MPAD * MLPD];

__device__ __align__(16) __nv_bfloat16 g_wp_hi  [DIM * PD];
__device__ __align__(16) __nv_bfloat16 g_wp_lo  [DIM * PD];
__device__ __align__(16) __nv_bfloat16 g_wqkv_hi[(size_t)DEPTH * TRI * DIM];
__device__ __align__(16) __nv_bfloat16 g_wqkv_lo[(size_t)DEPTH * TRI * DIM];
__device__ __align__(16) __nv_bfloat16 g_wout_hi[(size_t)DEPTH * DIM * INNER];
__device__ __align__(16) __nv_bfloat16 g_wout_lo[(size_t)DEPTH * DIM * INNER];
__device__ __align__(16) __nv_bfloat16 g_wf1_hi [(size_t)DEPTH * MLPD * DIM];
__device__ __align__(16) __nv_bfloat16 g_wf1_lo [(size_t)DEPTH * MLPD * DIM];
__device__ __align__(16) __nv_bfloat16 g_wf2_hi [(size_t)DEPTH * DIM * MLPD];
__device__ __align__(16) __nv_bfloat16 g_wf2_lo [(size_t)DEPTH * DIM * MLPD];

// ---------------- helpers ----------------
__device__ __forceinline__ uint32_t smem_u32(const void* p) {
    uint32_t a;
    asm("{ .reg .u64 t; cvta.to.shared.u64 t, %1; cvt.u32.u64 %0, t; }" : "=r"(a) : "l"(p));
    return a;
}
__device__ __forceinline__ void cp_async16(uint32_t dst, const void* src) {
    asm volatile("cp.async.cg.shared.global [%0], [%1], 16;" :: "r"(dst), "l"(src));
}
__device__ __forceinline__ void cp_commit() {
    asm volatile("cp.async.commit_group;" ::: "memory");
}
template <int N>
__device__ __forceinline__ void cp_wait() {
    asm volatile("cp.async.wait_group %0;" :: "n"(N) : "memory");
}
__device__ __forceinline__ void ldsm4(uint32_t* r, uint32_t a) {
    asm volatile("ldmatrix.sync.aligned.m8n8.x4.shared.b16 {%0,%1,%2,%3}, [%4];"
        : "=r"(r[0]), "=r"(r[1]), "=r"(r[2]), "=r"(r[3]) : "r"(a));
}
__device__ __forceinline__ void mma_bf16(float* c, const uint32_t* a, const uint32_t* b) {
    asm volatile(
        "mma.sync.aligned.m16n8k16.row.col.f32.bf16.bf16.f32 "
        "{%0,%1,%2,%3},{%4,%5,%6,%7},{%8,%9},{%0,%1,%2,%3};"
        : "+f"(c[0]), "+f"(c[1]), "+f"(c[2]), "+f"(c[3])
        : "r"(a[0]), "r"(a[1]), "r"(a[2]), "r"(a[3]), "r"(b[0]), "r"(b[1]));
}
__device__ __forceinline__ void split_val(float v, __nv_bfloat16& h, __nv_bfloat16& l) {
    h = __float2bfloat16(v);
    l = __float2bfloat16(v - __bfloat162float(h));
}

// ---------------- split weights (vectorized x4) ----------------
__global__ void split_kernel(const float4* __restrict__ in,
                             __nv_bfloat162* __restrict__ hi,
                             __nv_bfloat162* __restrict__ lo, size_t n4) {
    size_t i = (size_t)blockIdx.x * blockDim.x + threadIdx.x;
    if (i >= n4) return;
    float4 v = in[i];
    __nv_bfloat16 hx, lx, hy, ly, hz, lz, hw, lw;
    split_val(v.x, hx, lx); split_val(v.y, hy, ly);
    split_val(v.z, hz, lz); split_val(v.w, hw, lw);
    hi[2*i]   = __nv_bfloat162(hx, hy);
    hi[2*i+1] = __nv_bfloat162(hz, hw);
    lo[2*i]   = __nv_bfloat162(lx, ly);
    lo[2*i+1] = __nv_bfloat162(lz, lw);
}

// ---------------- channel-mean image ----------------
__global__ void mean_kernel(const float* __restrict__ img) {
    int idx = blockIdx.x * blockDim.x + threadIdx.x;
    if (idx >= BATCH * IMG * IMG) return;
    int b = idx / (IMG * IMG);
    int hw = idx % (IMG * IMG);
    const float* p = img + (size_t)b * 3 * IMG * IMG + hw;
    g_mean[idx] = (p[0] + p[(size_t)IMG*IMG] + p[(size_t)2*IMG*IMG]) * (1.0f / 3.0f);
}

// ---------------- patch extraction -> split bf16 ----------------
__global__ void patches_kernel(const float* __restrict__ img) {
    size_t idx = (size_t)blockIdx.x * blockDim.x + threadIdx.x;
    if (idx >= (size_t)MPE * PD) return;
    int pd = (int)(idx % PD);
    int n  = (int)((idx / PD) % NPAT);
    int b  = (int)(idx / ((size_t)PD * NPAT));
    int ch = pd % 7;
    int pp = pd / 7;
    int pr = pp / PCH, pc = pp % PCH;
    int gr = n / GRD,  gc = n % GRD;
    int hh = gr * PCH + pr;
    int ww = gc * PCH + pc;
    float v;
    if (ch < 3) {
        v = img[(((size_t)b * 3 + ch) * IMG + hh) * IMG + ww];
    } else {
        int sh = hh, sw = ww;
        if (ch == 3) sw = ww - SHIFT;
        else if (ch == 4) sw = ww + SHIFT;
        else if (ch == 5) sh = hh - SHIFT;
        else              sh = hh + SHIFT;
        if (sh < 0 || sh >= IMG || sw < 0 || sw >= IMG) v = 0.0f;
        else v = g_mean[((size_t)b * IMG + sh) * IMG + sw];
    }
    split_val(v, g_act1_hi[idx], g_act1_lo[idx]);
}

// ---------------- HMMA split-bf16 GEMM (swizzled, 3-stage, 1 barrier/chunk) --------
template <int EPI>
__global__ __launch_bounds__(256, 2)
void mma_gemm(const __nv_bfloat16* __restrict__ Ahi, const __nv_bfloat16* __restrict__ Alo,
              const __nv_bfloat16* __restrict__ Whi, const __nv_bfloat16* __restrict__ Wlo,
              const float* __restrict__ bias, const float* __restrict__ res,
              float* __restrict__ C, __nv_bfloat16* __restrict__ Chi,
              __nv_bfloat16* __restrict__ Clo, int N, int K) {
    extern __shared__ char sm[];
    uint32_t sbase = smem_u32(sm);
    int tid = threadIdx.x, wid = tid >> 5, lane = tid & 31;
    int wm = wid & 3, wn = wid >> 2;
    int m0 = blockIdx.y * 128, n0 = blockIdx.x * 128;

    const __nv_bfloat16* ah = Ahi + (size_t)m0 * K;
    const __nv_bfloat16* al = Alo + (size_t)m0 * K;
    const __nv_bfloat16* wh = Whi + (size_t)n0 * K;
    const __nv_bfloat16* wl = Wlo + (size_t)n0 * K;
    int nch = K / BK;

    float acc[2][8][4];
#pragma unroll
    for (int i = 0; i < 2; i++)
#pragma unroll
        for (int j = 0; j < 8; j++)
#pragma unroll
            for (int q = 0; q < 4; q++) acc[i][j][q] = 0.0f;

    int l_row = tid >> 1, l_half = tid & 1;
    const __nv_bfloat16* l_srcA = (l_half ? al : ah) + (size_t)l_row * K;
    const __nv_bfloat16* l_srcW = (l_half ? wl : wh) + (size_t)l_row * K;

    auto load_st = [&](int st, int c) {
        uint32_t dstb = sbase + st * STAGE_B;
        int ko = c * BK;
#pragma unroll
        for (int j = 0; j < 4; j++) {
            uint32_t off = l_row * 128 + (l_half * 4 + j) * 16;
            uint32_t d = SWZ(off);
            cp_async16(dstb + d,           l_srcA + ko + j * 8);
            cp_async16(dstb + TILE128 + d, l_srcW + ko + j * 8);
        }
        cp_commit();
    };

    // fragment row/col bases
    int a_r  = (lane & 15);                      // + wm*32 + mt*16
    int a_cb = (lane >> 4);                      // + kk*2, +4 for lo
    int w_r  = ((lane >> 4) << 3) + (lane & 7);  // + wn*64 + ng*16
    int w_cb = ((lane >> 3) & 1);                // + kk*2, +4 for lo

    load_st(0, 0);
    if (nch > 1) load_st(1, 1); else cp_commit();

    int st = 0;
    for (int c = 0; c < nch; c++) {
        cp_wait<1>();
        __syncthreads();
        uint32_t ab = sbase + st * STAGE_B;
        uint32_t bb = ab + TILE128;
#pragma unroll
        for (int kk = 0; kk < 2; kk++) {
            uint32_t ahr[2][4], alr[2][4];
#pragma unroll
            for (int mt = 0; mt < 2; mt++) {
                int r = wm * 32 + mt * 16 + a_r;
                int ch = kk * 2 + a_cb;
                ldsm4(ahr[mt], ab + r * 128 + ((ch       ^ (r & 7)) * 16));
                ldsm4(alr[mt], ab + r * 128 + (((ch + 4) ^ (r & 7)) * 16));
            }
#pragma unroll
            for (int ng = 0; ng < 4; ng++) {
                int r = wn * 64 + ng * 16 + w_r;
                int ch = kk * 2 + w_cb;
                uint32_t rh[4], rl[4];
                ldsm4(rh, bb + r * 128 + ((ch       ^ (r & 7)) * 16));
                ldsm4(rl, bb + r * 128 + (((ch + 4) ^ (r & 7)) * 16));
#pragma unroll
                for (int half = 0; half < 2; half++) {
                    int nt = ng * 2 + half;
                    uint32_t bh[2] = { rh[half*2], rh[half*2+1] };
                    uint32_t bl[2] = { rl[half*2], rl[half*2+1] };
#pragma unroll
                    for (int mt = 0; mt < 2; mt++) {
                        mma_bf16(acc[mt][nt], ahr[mt], bh);
                        mma_bf16(acc[mt][nt], ahr[mt], bl);
                        mma_bf16(acc[mt][nt], alr[mt], bh);
                    }
                }
            }
        }
        // slot (c+2)%3 != current, != in-flight-next; top barrier of iter c already
        // guaranteed all warps finished chunk c-1 (the previous occupant). Safe.
        if (c + 2 < nch) {
            int st2 = st + 2; if (st2 >= 3) st2 -= 3;
            load_st(st2, c + 2);
        } else cp_commit();
        if (++st == 3) st = 0;
    }

    int gid = lane >> 2;
    int cpr = (lane & 3) * 2;
#pragma unroll
    for (int mt = 0; mt < 2; mt++) {
        int r0 = m0 + wm * 32 + mt * 16 + gid;
        int r1 = r0 + 8;
#pragma unroll
        for (int nt = 0; nt < 8; nt++) {
            int n = n0 + wn * 64 + nt * 8 + cpr;
            float b0 = bias ? bias[n] : 0.0f;
            float b1 = bias ? bias[n + 1] : 0.0f;
            float v00 = acc[mt][nt][0] + b0, v01 = acc[mt][nt][1] + b1;
            float v10 = acc[mt][nt][2] + b0, v11 = acc[mt][nt][3] + b1;
            size_t o0 = (size_t)r0 * N + n;
            size_t o1 = (size_t)r1 * N + n;
            if (EPI == 1) {
                v00 = 0.5f * v00 * (1.0f + erff(v00 * 0.70710678118654752f));
                v01 = 0.5f * v01 * (1.0f + erff(v01 * 0.70710678118654752f));
                v10 = 0.5f * v10 * (1.0f + erff(v10 * 0.70710678118654752f));
                v11 = 0.5f * v11 * (1.0f + erff(v11 * 0.70710678118654752f));
                split_val(v00, Chi[o0], Clo[o0]);
                split_val(v01, Chi[o0 + 1], Clo[o0 + 1]);
                split_val(v10, Chi[o1], Clo[o1]);
                split_val(v11, Chi[o1 + 1], Clo[o1 + 1]);
            } else if (EPI == 2) {
                float2 r0v = *(const float2*)(res + o0);
                float2 r1v = *(const float2*)(res + o1);
                *(float2*)(C + o0) = make_float2(v00 + r0v.x, v01 + r0v.y);
                *(float2*)(C + o1) = make_float2(v10 + r1v.x, v11 + r1v.y);
            } else {
                *(float2*)(C + o0) = make_float2(v00, v01);
                *(float2*)(C + o1) = make_float2(v10, v11);
            }
        }
    }
}

// ---------------- assemble tokens ----------------
__global__ void assemble_kernel(const float* __restrict__ cls_tok,
                                const float* __restrict__ pos) {
    size_t idx = (size_t)blockIdx.x * blockDim.x + threadIdx.x;
    if (idx >= (size_t)BATCH * NT * DIM) return;
    int d = (int)(idx % DIM);
    int n = (int)((idx / DIM) % NT);
    int b = (int)(idx / ((size_t)DIM * NT));
    float v = (n == 0) ? cls_tok[d] : g_emb[((size_t)b * NPAT + (n - 1)) * DIM + d];
    g_x[idx] = v + pos[(size_t)n * DIM + d];
}

// ---------------- layernorm -> split bf16 (96 threads, float4) ----------------
__global__ void ln_split_kernel(const float* __restrict__ in, const float* __restrict__ g,
                                const float* __restrict__ be,
                                __nv_bfloat16* __restrict__ hi,
                                __nv_bfloat16* __restrict__ lo) {
    __shared__ float sh1[3], sh2[3];
    int row = blockIdx.x, tid = threadIdx.x;        // 96 threads
    int wrp = tid >> 5, lane = tid & 31;
    float4 v = ((const float4*)(in + (size_t)row * DIM))[tid];
    float s = v.x + v.y + v.z + v.w;
#pragma unroll
    for (int o = 16; o; o >>= 1) s += __shfl_xor_sync(0xFFFFFFFFu, s, o);
    if (lane == 0) sh1[wrp] = s;
    __syncthreads();
    float mu = (sh1[0] + sh1[1] + sh1[2]) * (1.0f / DIM);
    float dx = v.x - mu, dy = v.y - mu, dz = v.z - mu, dw = v.w - mu;
    float var = dx*dx + dy*dy + dz*dz + dw*dw;
#pragma unroll
    for (int o = 16; o; o >>= 1) var += __shfl_xor_sync(0xFFFFFFFFu, var, o);
    if (lane == 0) sh2[wrp] = var;
    __syncthreads();
    float rstd = rsqrtf((sh2[0] + sh2[1] + sh2[2]) * (1.0f / DIM) + LNEPS);
    float4 gv = ((const float4*)g)[tid];
    float4 bv = ((const float4*)be)[tid];
    float y0 = dx * rstd * gv.x + bv.x;
    float y1 = dy * rstd * gv.y + bv.y;
    float y2 = dz * rstd * gv.z + bv.z;
    float y3 = dw * rstd * gv.w + bv.w;
    __nv_bfloat16 h0,l0,h1,l1,h2,l2,h3,l3;
    split_val(y0,h0,l0); split_val(y1,h1,l1); split_val(y2,h2,l2); split_val(y3,h3,l3);
    __nv_bfloat162 hp[2] = { __nv_bfloat162(h0,h1), __nv_bfloat162(h2,h3) };
    __nv_bfloat162 lp[2] = { __nv_bfloat162(l0,l1), __nv_bfloat162(l2,l3) };
    ((uint2*)(hi + (size_t)row * DIM))[tid] = *(uint2*)hp;
    ((uint2*)(lo + (size_t)row * DIM))[tid] = *(uint2*)lp;
}

// ---------------- layernorm fp32 (final, strided input) ----------------
__global__ void ln_kernel(const float* __restrict__ in, const float* __restrict__ g,
                          const float* __restrict__ be, float* __restrict__ out,
                          size_t in_stride) {
    __shared__ float sh1[4], sh2[4];
    int row = blockIdx.x, tid = threadIdx.x;
    const float* x = in + (size_t)row * in_stride;
    float v0 = x[tid], v1 = x[tid + 128], v2 = x[tid + 256];
    float s = v0 + v1 + v2;
#pragma unroll
    for (int o = 16; o; o >>= 1) s += __shfl_xor_sync(0xFFFFFFFFu, s, o);
    if ((tid & 31) == 0) sh1[tid >> 5] = s;
    __syncthreads();
    float mu = (sh1[0] + sh1[1] + sh1[2] + sh1[3]) * (1.0f / DIM);
    float d0 = v0 - mu, d1 = v1 - mu, d2 = v2 - mu;
    float var = d0*d0 + d1*d1 + d2*d2;
#pragma unroll
    for (int o = 16; o; o >>= 1) var += __shfl_xor_sync(0xFFFFFFFFu, var, o);
    if ((tid & 31) == 0) sh2[tid >> 5] = var;
    __syncthreads();
    float rstd = rsqrtf((sh2[0] + sh2[1] + sh2[2] + sh2[3]) * (1.0f / DIM) + LNEPS);
    float* y = out + (size_t)row * DIM;
    y[tid]       = d0 * rstd * g[tid]       + be[tid];
    y[tid + 128] = d1 * rstd * g[tid + 128] + be[tid + 128];
    y[tid + 256] = d2 * rstd * g[tid + 256] + be[tid + 256];
}

// ---------------- attention: one block per (b,h), warp-autonomous rows ----------------
__global__ __launch_bounds__(256, 2)
void attn_kernel(const float* __restrict__ scale, int layer) {
    extern __shared__ float smf[];
    float* kT = smf;
    float* vT = kT + ATTN_KT_FLOATS;
    float* pw = vT + ATTN_VT_FLOATS;

    int bh = blockIdx.x;
    int b = bh / NH, hd = bh % NH;
    int tid = threadIdx.x, wid = tid >> 5, lane = tid & 31;
    float sc = scale[layer * NH + hd];
    const float* base = g_qkv + (size_t)b * NT * TRI;

    for (int t = tid; t < NT * DHD; t += 256) {
        int n = t >> 5, d = t & 31;
        kT[d * KT_STRIDE + n] = base[(size_t)n * TRI +     INNER + hd * DHD + d];
        vT[d * VT_STRIDE + n] = base[(size_t)n * TRI + 2 * INNER + hd * DHD + d];
    }
    for (int t = tid; t < DHD * (VT_STRIDE - NT); t += 256) {
        int d = t / (VT_STRIDE - NT), n = NT + t % (VT_STRIDE - NT);
        vT[d * VT_STRIDE + n] = 0.0f;
    }
    __syncthreads();

    float* pr = pw + wid * 4 * 224;

    for (int base_row = wid * 4; base_row < NT; base_row += 32) {
        float q0, q1, q2, q3;
        {
            int i0 = base_row, i1 = base_row + 1, i2 = base_row + 2, i3 = base_row + 3;
            q0 = (i0 < NT) ? base[(size_t)i0 * TRI + hd * DHD + lane] : 0.0f;
            q1 = (i1 < NT) ? base[(size_t)i1 * TRI + hd * DHD + lane] : 0.0f;
            q2 = (i2 < NT) ? base[(size_t)i2 * TRI + hd * DHD + lane] : 0.0f;
            q3 = (i3 < NT) ? base[(size_t)i3 * TRI + hd * DHD + lane] : 0.0f;
        }
        float s[4][7];
#pragma unroll
        for (int r = 0; r < 4; r++)
#pragma unroll
            for (int t = 0; t < 7; t++) s[r][t] = 0.0f;

#pragma unroll
        for (int d = 0; d < 32; d++) {
            float a0 = __shfl_sync(0xFFFFFFFFu, q0, d);
            float a1 = __shfl_sync(0xFFFFFFFFu, q1, d);
            float a2 = __shfl_sync(0xFFFFFFFFu, q2, d);
            float a3 = __shfl_sync(0xFFFFFFFFu, q3, d);
            const float* krow = kT + d * KT_STRIDE + lane;
#pragma unroll
            for (int t = 0; t < 7; t++) {
                float kv = krow[32 * t];
                s[0][t] = fmaf(a0, kv, s[0][t]);
                s[1][t] = fmaf(a1, kv, s[1][t]);
                s[2][t] = fmaf(a2, kv, s[2][t]);
                s[3][t] = fmaf(a3, kv, s[3][t]);
            }
        }

#pragma unroll
        for (int r = 0; r < 4; r++) {
            int i = base_row + r;
            float mx = -INFINITY;
#pragma unroll
            for (int t = 0; t < 7; t++) {
                int j = lane + 32 * t;
                if (j >= NT || j == i) s[r][t] = -INFINITY;
                mx = fmaxf(mx, s[r][t]);
            }
#pragma unroll
            for (int o = 16; o; o >>= 1) mx = fmaxf(mx, __shfl_xor_sync(0xFFFFFFFFu, mx, o));
            float su = 0.0f;
#pragma unroll
            for (int t = 0; t < 7; t++) {
                float p = __expf((s[r][t] - mx) * sc);
                s[r][t] = p;
                su += p;
            }
#pragma unroll
            for (int o = 16; o; o >>= 1) su += __shfl_xor_sync(0xFFFFFFFFu, su, o);
            float inv = 1.0f / su;
#pragma unroll
            for (int t = 0; t < 7; t++)
                pr[r * 224 + lane + 32 * t] = s[r][t] * inv;
        }
        __syncwarp();

        float c0 = 0.0f, c1 = 0.0f, c2 = 0.0f, c3 = 0.0f;
        const float* vrow = vT + lane * VT_STRIDE;
        for (int jj = 0; jj < 200; jj += 4) {
            float4 vv = *(const float4*)(vrow + jj);
            float4 p0 = *(const float4*)(pr + 0 * 224 + jj);
            float4 p1 = *(const float4*)(pr + 1 * 224 + jj);
            float4 p2 = *(const float4*)(pr + 2 * 224 + jj);
            float4 p3 = *(const float4*)(pr + 3 * 224 + jj);
            c0 += p0.x*vv.x + p0.y*vv.y + p0.z*vv.z + p0.w*vv.w;
            c1 += p1.x*vv.x + p1.y*vv.y + p1.z*vv.z + p1.w*vv.w;
            c2 += p2.x*vv.x + p2.y*vv.y + p2.z*vv.z + p2.w*vv.w;
            c3 += p3.x*vv.x + p3.y*vv.y + p3.z*vv.z + p3.w*vv.w;
        }
        float accs[4] = {c0, c1, c2, c3};
#pragma unroll
        for (int r = 0; r < 4; r++) {
            int i = base_row + r;
            if (i < NT) {
                size_t o = ((size_t)b * NT + i) * INNER + hd * DHD + lane;
                split_val(accs[r], g_act2_hi[o], g_act2_lo[o]);
            }
        }
        __syncwarp();
    }
}

// ---------------- classifier head ----------------
__global__ void head_kernel(const float* __restrict__ w, const float* __restrict__ bias,
                            float* __restrict__ out) {
    int b = blockIdx.y;
    int n = blockIdx.x * blockDim.x + threadIdx.x;
    if (n >= NCLS) return;
    const float* xr = g_cls + (size_t)b * DIM;
    const float* wr = w + (size_t)n * DIM;
    float acc = 0.0f;
    for (int k = 0; k < DIM; k++) acc += xr[k] * wr[k];
    out[(size_t)b * NCLS + n] = acc + bias[n];
}

// ---------------- host launch ----------------
extern "C" void kernel_launch(void* const* d_in, const int* in_sizes, int n_in,
                              void* d_out, int out_size) {
    const float* img     = (const float*)d_in[0];
    const float* patch_w = (const float*)d_in[1];
    const float* patch_b = (const float*)d_in[2];
    const float* pos_emb = (const float*)d_in[3];
    const float* cls_tok = (const float*)d_in[4];
    const float* ln1_g   = (const float*)d_in[5];
    const float* ln1_b   = (const float*)d_in[6];
    const float* qkv_w   = (const float*)d_in[7];
    const float* scale   = (const float*)d_in[8];
    const float* out_w   = (const float*)d_in[9];
    const float* out_b   = (const float*)d_in[10];
    const float* ln2_g   = (const float*)d_in[11];
    const float* ln2_b   = (const float*)d_in[12];
    const float* ff_w1   = (const float*)d_in[13];
    const float* ff_b1   = (const float*)d_in[14];
    const float* ff_w2   = (const float*)d_in[15];
    const float* ff_b2   = (const float*)d_in[16];
    const float* lnf_g   = (const float*)d_in[17];
    const float* lnf_b   = (const float*)d_in[18];
    const float* head_w  = (const float*)d_in[19];
    const float* head_b  = (const float*)d_in[20];
    float* out = (float*)d_out;

    float *p_emb, *p_x, *p_qkv, *p_cls;
    __nv_bfloat16 *a1h, *a1l, *a2h, *a2l;
    __nv_bfloat16 *wph, *wpl, *wqh, *wql, *woh, *wol, *w1h, *w1l, *w2h, *w2l;
    cudaGetSymbolAddress((void**)&p_emb, g_emb);
    cudaGetSymbolAddress((void**)&p_x,   g_x);
    cudaGetSymbolAddress((void**)&p_qkv, g_qkv);
    cudaGetSymbolAddress((void**)&p_cls, g_cls);
    cudaGetSymbolAddress((void**)&a1h, g_act1_hi);
    cudaGetSymbolAddress((void**)&a1l, g_act1_lo);
    cudaGetSymbolAddress((void**)&a2h, g_act2_hi);
    cudaGetSymbolAddress((void**)&a2l, g_act2_lo);
    cudaGetSymbolAddress((void**)&wph, g_wp_hi);
    cudaGetSymbolAddress((void**)&wpl, g_wp_lo);
    cudaGetSymbolAddress((void**)&wqh, g_wqkv_hi);
    cudaGetSymbolAddress((void**)&wql, g_wqkv_lo);
    cudaGetSymbolAddress((void**)&woh, g_wout_hi);
    cudaGetSymbolAddress((void**)&wol, g_wout_lo);
    cudaGetSymbolAddress((void**)&w1h, g_wf1_hi);
    cudaGetSymbolAddress((void**)&w1l, g_wf1_lo);
    cudaGetSymbolAddress((void**)&w2h, g_wf2_hi);
    cudaGetSymbolAddress((void**)&w2l, g_wf2_lo);

    cudaFuncSetAttribute(attn_kernel, cudaFuncAttributeMaxDynamicSharedMemorySize, ATTN_SMEM_BYTES);
    cudaFuncSetAttribute(mma_gemm<0>, cudaFuncAttributeMaxDynamicSharedMemorySize, GEMM_SMEM);
    cudaFuncSetAttribute(mma_gemm<1>, cudaFuncAttributeMaxDynamicSharedMemorySize, GEMM_SMEM);
    cudaFuncSetAttribute(mma_gemm<2>, cudaFuncAttributeMaxDynamicSharedMemorySize, GEMM_SMEM);

    auto SPLIT = [&](const float* src, __nv_bfloat16* h, __nv_bfloat16* l, size_t n) {
        split_kernel<<<(unsigned)((n / 4 + 255) / 256), 256>>>(
            (const float4*)src, (__nv_bfloat162*)h, (__nv_bfloat162*)l, n / 4);
    };

    // Keep launch index 3 (ncu capture) = patch-embed GEMM.
    mean_kernel<<<(BATCH * IMG * IMG + 255) / 256, 256>>>(img);                       // 0
    patches_kernel<<<(unsigned)(((size_t)MPE * PD + 255) / 256), 256>>>(img);         // 1
    SPLIT(patch_w, wph, wpl, (size_t)DIM * PD);                                       // 2
    mma_gemm<0><<<dim3(DIM / 128, MPE / 128), 256, GEMM_SMEM>>>(                      // 3 <- ncu
        a1h, a1l, wph, wpl, patch_b, nullptr, p_emb, nullptr, nullptr, DIM, PD);
    SPLIT(qkv_w,   wqh, wql, (size_t)DEPTH * TRI * DIM);
    SPLIT(out_w,   woh, wol, (size_t)DEPTH * DIM * INNER);
    SPLIT(ff_w1,   w1h, w1l, (size_t)DEPTH * MLPD * DIM);
    SPLIT(ff_w2,   w2h, w2l, (size_t)DEPTH * DIM * MLPD);
    assemble_kernel<<<(unsigned)(((size_t)BATCH * NT * DIM + 255) / 256), 256>>>(cls_tok, pos_emb);

    for (int l = 0; l < DEPTH; l++) {
        const __nv_bfloat16* lqh = wqh + (size_t)l * TRI * DIM;
        const __nv_bfloat16* lql = wql + (size_t)l * TRI * DIM;
        const __nv_bfloat16* loh = woh + (size_t)l * DIM * INNER;
        const __nv_bfloat16* lol = wol + (size_t)l * DIM * INNER;
        const __nv_bfloat16* l1h = w1h + (size_t)l * MLPD * DIM;
        const __nv_bfloat16* l1l = w1l + (size_t)l * MLPD * DIM;
        const __nv_bfloat16* l2h = w2h + (size_t)l * DIM * MLPD;
        const __nv_bfloat16* l2l = w2l + (size_t)l * DIM * MLPD;

        ln_split_kernel<<<MROWS, 96>>>(p_x, ln1_g + (size_t)l * DIM, ln1_b + (size_t)l * DIM, a1h, a1l);
        mma_gemm<0><<<dim3(TRI / 128, MPAD / 128), 256, GEMM_SMEM>>>(
            a1h, a1l, lqh, lql, nullptr, nullptr, p_qkv, nullptr, nullptr, TRI, DIM);
        attn_kernel<<<BATCH * NH, 256, ATTN_SMEM_BYTES>>>(scale, l);
        mma_gemm<2><<<dim3(DIM / 128, MPAD / 128), 256, GEMM_SMEM>>>(
            a2h, a2l, loh, lol, out_b + (size_t)l * DIM, p_x, p_x, nullptr, nullptr, DIM, INNER);
        ln_split_kernel<<<MROWS, 96>>>(p_x, ln2_g + (size_t)l * DIM, ln2_b + (size_t)l * DIM, a1h, a1l);
        mma_gemm<1><<<dim3(MLPD / 128, MPAD / 128), 256, GEMM_SMEM>>>(
            a1h, a1l, l1h, l1l, ff_b1 + (size_t)l * MLPD, nullptr, nullptr, a2h, a2l, MLPD, DIM);
        mma_gemm<2><<<dim3(DIM / 128, MPAD / 128), 256, GEMM_SMEM>>>(
            a2h, a2l, l2h, l2l, ff_b2 + (size_t)l * DIM, p_x, p_x, nullptr, nullptr, DIM, MLPD);
    }

    ln_kernel<<<BATCH, 128>>>(p_x, lnf_g, lnf_b, p_cls, (size_t)NT * DIM);
    head_kernel<<<dim3((NCLS + 255) / 256, BATCH), 256>>>(head_w, head_b, out);
}

// round 10
// speedup vs baseline: 1.0034x; 1.0034x over previous
#include <cuda_runtime.h>
#include <cuda_bf16.h>
#include <math.h>
#include <cstdint>

// ---------------- problem constants ----------------
constexpr int BATCH = 64;
constexpr int IMG   = 224;
constexpr int PCH   = 16;
constexpr int SHIFT = 8;
constexpr int GRD   = 14;
constexpr int NPAT  = 196;
constexpr int NT    = 197;
constexpr int DIM   = 384;
constexpr int DEPTH = 12;
constexpr int NH    = 12;
constexpr int DHD   = 32;
constexpr int INNER = 384;
constexpr int TRI   = 1152;
constexpr int MLPD  = 1536;
constexpr int NCLS  = 1000;
constexpr int PD    = 1792;
constexpr float LNEPS = 1e-5f;

constexpr int MROWS = BATCH * NT;            // 12608
constexpr int MPAD  = 12672;                 // 99 * 128
constexpr int MPE   = BATCH * NPAT;          // 12544 = 98 * 128

// ---------------- attention smem layout ----------------
constexpr int KT_STRIDE = 225;
constexpr int VT_STRIDE = 228;
constexpr int ATTN_KT_FLOATS = DHD * KT_STRIDE;
constexpr int ATTN_VT_FLOATS = DHD * VT_STRIDE;
constexpr int ATTN_PW_FLOATS = 8 * 4 * 224;
constexpr int ATTN_SMEM_BYTES = (ATTN_KT_FLOATS + ATTN_VT_FLOATS + ATTN_PW_FLOATS) * 4;

// ---------------- GEMM tile config ----------------
// Row = 144B: hi 32xbf16 at [0,64), lo at [64,128), 16B pad. Stride 144 ->
// ldmatrix 8-row phases hit quads (9r mod 8)=r mod 8: conflict-free (proven
// pattern, same family as the 80B rows of round 8).
// Stage = A tile (18432B) + W tile (18432B) = 36864B; 3 stages = 110592B -> 2 CTAs/SM.
constexpr int BK      = 32;
constexpr int ROW2    = 144;
constexpr int TILE2   = 128 * ROW2;           // 18432
constexpr int STAGE_B = 2 * TILE2;            // 36864
constexpr int STAGES  = 3;
constexpr int GEMM_SMEM = STAGES * STAGE_B;   // 110592

// ---------------- device scratch ----------------
__device__ float g_mean [BATCH * IMG * IMG];
__device__ float g_emb  [(size_t)MPE * DIM];
__device__ float g_x    [(size_t)MPAD * DIM];
__device__ float g_qkv  [(size_t)MPAD * TRI];
__device__ float g_cls  [BATCH * DIM];

__device__ __align__(16) __nv_bfloat16 g_act1_hi[(size_t)MPE * PD];
__device__ __align__(16) __nv_bfloat16 g_act1_lo[(size_t)MPE * PD];
__device__ __align__(16) __nv_bfloat16 g_act2_hi[(size_t)MPAD * MLPD];
__device__ __align__(16) __nv_bfloat16 g_act2_lo[(size_t)MPAD * MLPD];

__device__ __align__(16) __nv_bfloat16 g_wp_hi  [DIM * PD];
__device__ __align__(16) __nv_bfloat16 g_wp_lo  [DIM * PD];
__device__ __align__(16) __nv_bfloat16 g_wqkv_hi[(size_t)DEPTH * TRI * DIM];
__device__ __align__(16) __nv_bfloat16 g_wqkv_lo[(size_t)DEPTH * TRI * DIM];
__device__ __align__(16) __nv_bfloat16 g_wout_hi[(size_t)DEPTH * DIM * INNER];
__device__ __align__(16) __nv_bfloat16 g_wout_lo[(size_t)DEPTH * DIM * INNER];
__device__ __align__(16) __nv_bfloat16 g_wf1_hi [(size_t)DEPTH * MLPD * DIM];
__device__ __align__(16) __nv_bfloat16 g_wf1_lo [(size_t)DEPTH * MLPD * DIM];
__device__ __align__(16) __nv_bfloat16 g_wf2_hi [(size_t)DEPTH * DIM * MLPD];
__device__ __align__(16) __nv_bfloat16 g_wf2_lo [(size_t)DEPTH * DIM * MLPD];

// ---------------- helpers ----------------
__device__ __forceinline__ uint32_t smem_u32(const void* p) {
    uint32_t a;
    asm("{ .reg .u64 t; cvta.to.shared.u64 t, %1; cvt.u32.u64 %0, t; }" : "=r"(a) : "l"(p));
    return a;
}
__device__ __forceinline__ void cp_async16(uint32_t dst, const void* src) {
    asm volatile("cp.async.cg.shared.global [%0], [%1], 16;" :: "r"(dst), "l"(src));
}
__device__ __forceinline__ void cp_commit() {
    asm volatile("cp.async.commit_group;" ::: "memory");
}
template <int N>
__device__ __forceinline__ void cp_wait() {
    asm volatile("cp.async.wait_group %0;" :: "n"(N) : "memory");
}
__device__ __forceinline__ void ldsm4(uint32_t* r, uint32_t a) {
    asm volatile("ldmatrix.sync.aligned.m8n8.x4.shared.b16 {%0,%1,%2,%3}, [%4];"
        : "=r"(r[0]), "=r"(r[1]), "=r"(r[2]), "=r"(r[3]) : "r"(a));
}
__device__ __forceinline__ void mma_bf16(float* c, const uint32_t* a, const uint32_t* b) {
    asm volatile(
        "mma.sync.aligned.m16n8k16.row.col.f32.bf16.bf16.f32 "
        "{%0,%1,%2,%3},{%4,%5,%6,%7},{%8,%9},{%0,%1,%2,%3};"
        : "+f"(c[0]), "+f"(c[1]), "+f"(c[2]), "+f"(c[3])
        : "r"(a[0]), "r"(a[1]), "r"(a[2]), "r"(a[3]), "r"(b[0]), "r"(b[1]));
}
__device__ __forceinline__ void split_val(float v, __nv_bfloat16& h, __nv_bfloat16& l) {
    h = __float2bfloat16(v);
    l = __float2bfloat16(v - __bfloat162float(h));
}

// ---------------- split weights (vectorized x4) ----------------
__global__ void split_kernel(const float4* __restrict__ in,
                             __nv_bfloat162* __restrict__ hi,
                             __nv_bfloat162* __restrict__ lo, size_t n4) {
    size_t i = (size_t)blockIdx.x * blockDim.x + threadIdx.x;
    if (i >= n4) return;
    float4 v = in[i];
    __nv_bfloat16 hx, lx, hy, ly, hz, lz, hw, lw;
    split_val(v.x, hx, lx); split_val(v.y, hy, ly);
    split_val(v.z, hz, lz); split_val(v.w, hw, lw);
    hi[2*i]   = __nv_bfloat162(hx, hy);
    hi[2*i+1] = __nv_bfloat162(hz, hw);
    lo[2*i]   = __nv_bfloat162(lx, ly);
    lo[2*i+1] = __nv_bfloat162(lz, lw);
}

// ---------------- channel-mean image ----------------
__global__ void mean_kernel(const float* __restrict__ img) {
    int idx = blockIdx.x * blockDim.x + threadIdx.x;
    if (idx >= BATCH * IMG * IMG) return;
    int b = idx / (IMG * IMG);
    int hw = idx % (IMG * IMG);
    const float* p = img + (size_t)b * 3 * IMG * IMG + hw;
    g_mean[idx] = (p[0] + p[(size_t)IMG*IMG] + p[(size_t)2*IMG*IMG]) * (1.0f / 3.0f);
}

// ---------------- patch extraction -> split bf16 ----------------
__global__ void patches_kernel(const float* __restrict__ img) {
    size_t idx = (size_t)blockIdx.x * blockDim.x + threadIdx.x;
    if (idx >= (size_t)MPE * PD) return;
    int pd = (int)(idx % PD);
    int n  = (int)((idx / PD) % NPAT);
    int b  = (int)(idx / ((size_t)PD * NPAT));
    int ch = pd % 7;
    int pp = pd / 7;
    int pr = pp / PCH, pc = pp % PCH;
    int gr = n / GRD,  gc = n % GRD;
    int hh = gr * PCH + pr;
    int ww = gc * PCH + pc;
    float v;
    if (ch < 3) {
        v = img[(((size_t)b * 3 + ch) * IMG + hh) * IMG + ww];
    } else {
        int sh = hh, sw = ww;
        if (ch == 3) sw = ww - SHIFT;
        else if (ch == 4) sw = ww + SHIFT;
        else if (ch == 5) sh = hh - SHIFT;
        else              sh = hh + SHIFT;
        if (sh < 0 || sh >= IMG || sw < 0 || sw >= IMG) v = 0.0f;
        else v = g_mean[((size_t)b * IMG + sh) * IMG + sw];
    }
    split_val(v, g_act1_hi[idx], g_act1_lo[idx]);
}

// ---------------- HMMA split-bf16 GEMM ----------------
// 128x128 CTA tile, BK=32, 8 warps, 3-stage pipeline with load-at-top,
// one barrier per chunk, 2 CTAs/SM. Row layout: 144B (hi[0,64)|lo[64,128)|pad).
template <int EPI>
__global__ __launch_bounds__(256, 2)
void mma_gemm(const __nv_bfloat16* __restrict__ Ahi, const __nv_bfloat16* __restrict__ Alo,
              const __nv_bfloat16* __restrict__ Whi, const __nv_bfloat16* __restrict__ Wlo,
              const float* __restrict__ bias, const float* __restrict__ res,
              float* __restrict__ C, __nv_bfloat16* __restrict__ Chi,
              __nv_bfloat16* __restrict__ Clo, int N, int K) {
    extern __shared__ char sm[];
    uint32_t sbase = smem_u32(sm);
    int tid = threadIdx.x, wid = tid >> 5, lane = tid & 31;
    int wm = wid & 3, wn = wid >> 2;
    int m0 = blockIdx.y * 128, n0 = blockIdx.x * 128;

    const __nv_bfloat16* ah = Ahi + (size_t)m0 * K;
    const __nv_bfloat16* al = Alo + (size_t)m0 * K;
    const __nv_bfloat16* wh = Whi + (size_t)n0 * K;
    const __nv_bfloat16* wl = Wlo + (size_t)n0 * K;
    int nch = K / BK;

    float acc[2][8][4];
#pragma unroll
    for (int i = 0; i < 2; i++)
#pragma unroll
        for (int j = 0; j < 8; j++)
#pragma unroll
            for (int q = 0; q < 4; q++) acc[i][j][q] = 0.0f;

    // loader mapping: thread -> one row, hi or lo source, 4x16B per tile
    int l_row = tid >> 1, l_half = tid & 1;
    const __nv_bfloat16* l_srcA = (l_half ? al : ah) + (size_t)l_row * K;
    const __nv_bfloat16* l_srcW = (l_half ? wl : wh) + (size_t)l_row * K;
    uint32_t l_dst = l_row * ROW2 + l_half * 64;

    auto load_st = [&](int st, int c) {
        uint32_t dstb = sbase + st * STAGE_B + l_dst;
        int ko = c * BK;
#pragma unroll
        for (int j = 0; j < 4; j++) {
            cp_async16(dstb + j * 16,         l_srcA + ko + j * 8);
            cp_async16(dstb + TILE2 + j * 16, l_srcW + ko + j * 8);
        }
        cp_commit();
    };

    // fragment address bases (byte column within row: hi at col*2, lo at +64)
    int a_r  = (lane & 15);
    int a_cb = (lane >> 4) * 16;                   // byte offset of 8-k group
    int w_r  = ((lane >> 4) << 3) + (lane & 7);
    int w_cb = ((lane >> 3) & 1) * 16;

    load_st(0, 0);
    if (nch > 1) load_st(1, 1); else cp_commit();

    for (int c = 0; c < nch; c++) {
        cp_wait<1>();
        __syncthreads();
        // load chunk c+2 into slot (c+2)%3: held chunk c-1, finished by all
        // warps before this barrier; != compute slot c%3. Loads overlap MMAs.
        if (c + 2 < nch) load_st((c + 2) % 3, c + 2);
        else cp_commit();

        uint32_t ab = sbase + (c % 3) * STAGE_B;
        uint32_t bb = ab + TILE2;
#pragma unroll
        for (int kk = 0; kk < 2; kk++) {
            uint32_t ahr[2][4], alr[2][4];
#pragma unroll
            for (int mt = 0; mt < 2; mt++) {
                uint32_t addr = ab + (wm * 32 + mt * 16 + a_r) * ROW2 + kk * 32 + a_cb;
                ldsm4(ahr[mt], addr);
                ldsm4(alr[mt], addr + 64);
            }
#pragma unroll
            for (int ng = 0; ng < 4; ng++) {
                uint32_t addr = bb + (wn * 64 + ng * 16 + w_r) * ROW2 + kk * 32 + w_cb;
                uint32_t rh[4], rl[4];
                ldsm4(rh, addr);
                ldsm4(rl, addr + 64);
#pragma unroll
                for (int half = 0; half < 2; half++) {
                    int nt = ng * 2 + half;
                    uint32_t bh[2] = { rh[half*2], rh[half*2+1] };
                    uint32_t bl[2] = { rl[half*2], rl[half*2+1] };
#pragma unroll
                    for (int mt = 0; mt < 2; mt++) {
                        mma_bf16(acc[mt][nt], ahr[mt], bh);
                        mma_bf16(acc[mt][nt], ahr[mt], bl);
                        mma_bf16(acc[mt][nt], alr[mt], bh);
                    }
                }
            }
        }
    }

    int gid = lane >> 2;
    int cpr = (lane & 3) * 2;
#pragma unroll
    for (int mt = 0; mt < 2; mt++) {
        int r0 = m0 + wm * 32 + mt * 16 + gid;
        int r1 = r0 + 8;
#pragma unroll
        for (int nt = 0; nt < 8; nt++) {
            int n = n0 + wn * 64 + nt * 8 + cpr;
            float b0 = bias ? bias[n] : 0.0f;
            float b1 = bias ? bias[n + 1] : 0.0f;
            float v00 = acc[mt][nt][0] + b0, v01 = acc[mt][nt][1] + b1;
            float v10 = acc[mt][nt][2] + b0, v11 = acc[mt][nt][3] + b1;
            size_t o0 = (size_t)r0 * N + n;
            size_t o1 = (size_t)r1 * N + n;
            if (EPI == 1) {
                v00 = 0.5f * v00 * (1.0f + erff(v00 * 0.70710678118654752f));
                v01 = 0.5f * v01 * (1.0f + erff(v01 * 0.70710678118654752f));
                v10 = 0.5f * v10 * (1.0f + erff(v10 * 0.70710678118654752f));
                v11 = 0.5f * v11 * (1.0f + erff(v11 * 0.70710678118654752f));
                split_val(v00, Chi[o0], Clo[o0]);
                split_val(v01, Chi[o0 + 1], Clo[o0 + 1]);
                split_val(v10, Chi[o1], Clo[o1]);
                split_val(v11, Chi[o1 + 1], Clo[o1 + 1]);
            } else if (EPI == 2) {
                float2 r0v = *(const float2*)(res + o0);
                float2 r1v = *(const float2*)(res + o1);
                *(float2*)(C + o0) = make_float2(v00 + r0v.x, v01 + r0v.y);
                *(float2*)(C + o1) = make_float2(v10 + r1v.x, v11 + r1v.y);
            } else {
                *(float2*)(C + o0) = make_float2(v00, v01);
                *(float2*)(C + o1) = make_float2(v10, v11);
            }
        }
    }
}

// ---------------- assemble tokens ----------------
__global__ void assemble_kernel(const float* __restrict__ cls_tok,
                                const float* __restrict__ pos) {
    size_t idx = (size_t)blockIdx.x * blockDim.x + threadIdx.x;
    if (idx >= (size_t)BATCH * NT * DIM) return;
    int d = (int)(idx % DIM);
    int n = (int)((idx / DIM) % NT);
    int b = (int)(idx / ((size_t)DIM * NT));
    float v = (n == 0) ? cls_tok[d] : g_emb[((size_t)b * NPAT + (n - 1)) * DIM + d];
    g_x[idx] = v + pos[(size_t)n * DIM + d];
}

// ---------------- layernorm -> split bf16 (96 threads, float4) ----------------
__global__ void ln_split_kernel(const float* __restrict__ in, const float* __restrict__ g,
                                const float* __restrict__ be,
                                __nv_bfloat16* __restrict__ hi,
                                __nv_bfloat16* __restrict__ lo) {
    __shared__ float sh1[3], sh2[3];
    int row = blockIdx.x, tid = threadIdx.x;        // 96 threads
    int wrp = tid >> 5, lane = tid & 31;
    float4 v = ((const float4*)(in + (size_t)row * DIM))[tid];
    float s = v.x + v.y + v.z + v.w;
#pragma unroll
    for (int o = 16; o; o >>= 1) s += __shfl_xor_sync(0xFFFFFFFFu, s, o);
    if (lane == 0) sh1[wrp] = s;
    __syncthreads();
    float mu = (sh1[0] + sh1[1] + sh1[2]) * (1.0f / DIM);
    float dx = v.x - mu, dy = v.y - mu, dz = v.z - mu, dw = v.w - mu;
    float var = dx*dx + dy*dy + dz*dz + dw*dw;
#pragma unroll
    for (int o = 16; o; o >>= 1) var += __shfl_xor_sync(0xFFFFFFFFu, var, o);
    if (lane == 0) sh2[wrp] = var;
    __syncthreads();
    float rstd = rsqrtf((sh2[0] + sh2[1] + sh2[2]) * (1.0f / DIM) + LNEPS);
    float4 gv = ((const float4*)g)[tid];
    float4 bv = ((const float4*)be)[tid];
    float y0 = dx * rstd * gv.x + bv.x;
    float y1 = dy * rstd * gv.y + bv.y;
    float y2 = dz * rstd * gv.z + bv.z;
    float y3 = dw * rstd * gv.w + bv.w;
    __nv_bfloat16 h0,l0,h1,l1,h2,l2,h3,l3;
    split_val(y0,h0,l0); split_val(y1,h1,l1); split_val(y2,h2,l2); split_val(y3,h3,l3);
    __nv_bfloat162 hp[2] = { __nv_bfloat162(h0,h1), __nv_bfloat162(h2,h3) };
    __nv_bfloat162 lp[2] = { __nv_bfloat162(l0,l1), __nv_bfloat162(l2,l3) };
    ((uint2*)(hi + (size_t)row * DIM))[tid] = *(uint2*)hp;
    ((uint2*)(lo + (size_t)row * DIM))[tid] = *(uint2*)lp;
}

// ---------------- layernorm fp32 (final, strided input) ----------------
__global__ void ln_kernel(const float* __restrict__ in, const float* __restrict__ g,
                          const float* __restrict__ be, float* __restrict__ out,
                          size_t in_stride) {
    __shared__ float sh1[4], sh2[4];
    int row = blockIdx.x, tid = threadIdx.x;
    const float* x = in + (size_t)row * in_stride;
    float v0 = x[tid], v1 = x[tid + 128], v2 = x[tid + 256];
    float s = v0 + v1 + v2;
#pragma unroll
    for (int o = 16; o; o >>= 1) s += __shfl_xor_sync(0xFFFFFFFFu, s, o);
    if ((tid & 31) == 0) sh1[tid >> 5] = s;
    __syncthreads();
    float mu = (sh1[0] + sh1[1] + sh1[2] + sh1[3]) * (1.0f / DIM);
    float d0 = v0 - mu, d1 = v1 - mu, d2 = v2 - mu;
    float var = d0*d0 + d1*d1 + d2*d2;
#pragma unroll
    for (int o = 16; o; o >>= 1) var += __shfl_xor_sync(0xFFFFFFFFu, var, o);
    if ((tid & 31) == 0) sh2[tid >> 5] = var;
    __syncthreads();
    float rstd = rsqrtf((sh2[0] + sh2[1] + sh2[2] + sh2[3]) * (1.0f / DIM) + LNEPS);
    float* y = out + (size_t)row * DIM;
    y[tid]       = d0 * rstd * g[tid]       + be[tid];
    y[tid + 128] = d1 * rstd * g[tid + 128] + be[tid + 128];
    y[tid + 256] = d2 * rstd * g[tid + 256] + be[tid + 256];
}

// ---------------- attention: one block per (b,h), warp-autonomous rows ----------------
__global__ __launch_bounds__(256, 2)
void attn_kernel(const float* __restrict__ scale, int layer) {
    extern __shared__ float smf[];
    float* kT = smf;
    float* vT = kT + ATTN_KT_FLOATS;
    float* pw = vT + ATTN_VT_FLOATS;

    int bh = blockIdx.x;
    int b = bh / NH, hd = bh % NH;
    int tid = threadIdx.x, wid = tid >> 5, lane = tid & 31;
    float sc = scale[layer * NH + hd];
    const float* base = g_qkv + (size_t)b * NT * TRI;

    for (int t = tid; t < NT * DHD; t += 256) {
        int n = t >> 5, d = t & 31;
        kT[d * KT_STRIDE + n] = base[(size_t)n * TRI +     INNER + hd * DHD + d];
        vT[d * VT_STRIDE + n] = base[(size_t)n * TRI + 2 * INNER + hd * DHD + d];
    }
    for (int t = tid; t < DHD * (VT_STRIDE - NT); t += 256) {
        int d = t / (VT_STRIDE - NT), n = NT + t % (VT_STRIDE - NT);
        vT[d * VT_STRIDE + n] = 0.0f;
    }
    __syncthreads();

    float* pr = pw + wid * 4 * 224;

    for (int base_row = wid * 4; base_row < NT; base_row += 32) {
        float q0, q1, q2, q3;
        {
            int i0 = base_row, i1 = base_row + 1, i2 = base_row + 2, i3 = base_row + 3;
            q0 = (i0 < NT) ? base[(size_t)i0 * TRI + hd * DHD + lane] : 0.0f;
            q1 = (i1 < NT) ? base[(size_t)i1 * TRI + hd * DHD + lane] : 0.0f;
            q2 = (i2 < NT) ? base[(size_t)i2 * TRI + hd * DHD + lane] : 0.0f;
            q3 = (i3 < NT) ? base[(size_t)i3 * TRI + hd * DHD + lane] : 0.0f;
        }
        float s[4][7];
#pragma unroll
        for (int r = 0; r < 4; r++)
#pragma unroll
            for (int t = 0; t < 7; t++) s[r][t] = 0.0f;

#pragma unroll
        for (int d = 0; d < 32; d++) {
            float a0 = __shfl_sync(0xFFFFFFFFu, q0, d);
            float a1 = __shfl_sync(0xFFFFFFFFu, q1, d);
            float a2 = __shfl_sync(0xFFFFFFFFu, q2, d);
            float a3 = __shfl_sync(0xFFFFFFFFu, q3, d);
            const float* krow = kT + d * KT_STRIDE + lane;
#pragma unroll
            for (int t = 0; t < 7; t++) {
                float kv = krow[32 * t];
                s[0][t] = fmaf(a0, kv, s[0][t]);
                s[1][t] = fmaf(a1, kv, s[1][t]);
                s[2][t] = fmaf(a2, kv, s[2][t]);
                s[3][t] = fmaf(a3, kv, s[3][t]);
            }
        }

#pragma unroll
        for (int r = 0; r < 4; r++) {
            int i = base_row + r;
            float mx = -INFINITY;
#pragma unroll
            for (int t = 0; t < 7; t++) {
                int j = lane + 32 * t;
                if (j >= NT || j == i) s[r][t] = -INFINITY;
                mx = fmaxf(mx, s[r][t]);
            }
#pragma unroll
            for (int o = 16; o; o >>= 1) mx = fmaxf(mx, __shfl_xor_sync(0xFFFFFFFFu, mx, o));
            float su = 0.0f;
#pragma unroll
            for (int t = 0; t < 7; t++) {
                float p = __expf((s[r][t] - mx) * sc);
                s[r][t] = p;
                su += p;
            }
#pragma unroll
            for (int o = 16; o; o >>= 1) su += __shfl_xor_sync(0xFFFFFFFFu, su, o);
            float inv = 1.0f / su;
#pragma unroll
            for (int t = 0; t < 7; t++)
                pr[r * 224 + lane + 32 * t] = s[r][t] * inv;
        }
        __syncwarp();

        float c0 = 0.0f, c1 = 0.0f, c2 = 0.0f, c3 = 0.0f;
        const float* vrow = vT + lane * VT_STRIDE;
        for (int jj = 0; jj < 200; jj += 4) {
            float4 vv = *(const float4*)(vrow + jj);
            float4 p0 = *(const float4*)(pr + 0 * 224 + jj);
            float4 p1 = *(const float4*)(pr + 1 * 224 + jj);
            float4 p2 = *(const float4*)(pr + 2 * 224 + jj);
            float4 p3 = *(const float4*)(pr + 3 * 224 + jj);
            c0 += p0.x*vv.x + p0.y*vv.y + p0.z*vv.z + p0.w*vv.w;
            c1 += p1.x*vv.x + p1.y*vv.y + p1.z*vv.z + p1.w*vv.w;
            c2 += p2.x*vv.x + p2.y*vv.y + p2.z*vv.z + p2.w*vv.w;
            c3 += p3.x*vv.x + p3.y*vv.y + p3.z*vv.z + p3.w*vv.w;
        }
        float accs[4] = {c0, c1, c2, c3};
#pragma unroll
        for (int r = 0; r < 4; r++) {
            int i = base_row + r;
            if (i < NT) {
                size_t o = ((size_t)b * NT + i) * INNER + hd * DHD + lane;
                split_val(accs[r], g_act2_hi[o], g_act2_lo[o]);
            }
        }
        __syncwarp();
    }
}

// ---------------- classifier head ----------------
__global__ void head_kernel(const float* __restrict__ w, const float* __restrict__ bias,
                            float* __restrict__ out) {
    int b = blockIdx.y;
    int n = blockIdx.x * blockDim.x + threadIdx.x;
    if (n >= NCLS) return;
    const float* xr = g_cls + (size_t)b * DIM;
    const float* wr = w + (size_t)n * DIM;
    float acc = 0.0f;
    for (int k = 0; k < DIM; k++) acc += xr[k] * wr[k];
    out[(size_t)b * NCLS + n] = acc + bias[n];
}

// ---------------- host launch ----------------
extern "C" void kernel_launch(void* const* d_in, const int* in_sizes, int n_in,
                              void* d_out, int out_size) {
    const float* img     = (const float*)d_in[0];
    const float* patch_w = (const float*)d_in[1];
    const float* patch_b = (const float*)d_in[2];
    const float* pos_emb = (const float*)d_in[3];
    const float* cls_tok = (const float*)d_in[4];
    const float* ln1_g   = (const float*)d_in[5];
    const float* ln1_b   = (const float*)d_in[6];
    const float* qkv_w   = (const float*)d_in[7];
    const float* scale   = (const float*)d_in[8];
    const float* out_w   = (const float*)d_in[9];
    const float* out_b   = (const float*)d_in[10];
    const float* ln2_g   = (const float*)d_in[11];
    const float* ln2_b   = (const float*)d_in[12];
    const float* ff_w1   = (const float*)d_in[13];
    const float* ff_b1   = (const float*)d_in[14];
    const float* ff_w2   = (const float*)d_in[15];
    const float* ff_b2   = (const float*)d_in[16];
    const float* lnf_g   = (const float*)d_in[17];
    const float* lnf_b   = (const float*)d_in[18];
    const float* head_w  = (const float*)d_in[19];
    const float* head_b  = (const float*)d_in[20];
    float* out = (float*)d_out;

    float *p_emb, *p_x, *p_qkv, *p_cls;
    __nv_bfloat16 *a1h, *a1l, *a2h, *a2l;
    __nv_bfloat16 *wph, *wpl, *wqh, *wql, *woh, *wol, *w1h, *w1l, *w2h, *w2l;
    cudaGetSymbolAddress((void**)&p_emb, g_emb);
    cudaGetSymbolAddress((void**)&p_x,   g_x);
    cudaGetSymbolAddress((void**)&p_qkv, g_qkv);
    cudaGetSymbolAddress((void**)&p_cls, g_cls);
    cudaGetSymbolAddress((void**)&a1h, g_act1_hi);
    cudaGetSymbolAddress((void**)&a1l, g_act1_lo);
    cudaGetSymbolAddress((void**)&a2h, g_act2_hi);
    cudaGetSymbolAddress((void**)&a2l, g_act2_lo);
    cudaGetSymbolAddress((void**)&wph, g_wp_hi);
    cudaGetSymbolAddress((void**)&wpl, g_wp_lo);
    cudaGetSymbolAddress((void**)&wqh, g_wqkv_hi);
    cudaGetSymbolAddress((void**)&wql, g_wqkv_lo);
    cudaGetSymbolAddress((void**)&woh, g_wout_hi);
    cudaGetSymbolAddress((void**)&wol, g_wout_lo);
    cudaGetSymbolAddress((void**)&w1h, g_wf1_hi);
    cudaGetSymbolAddress((void**)&w1l, g_wf1_lo);
    cudaGetSymbolAddress((void**)&w2h, g_wf2_hi);
    cudaGetSymbolAddress((void**)&w2l, g_wf2_lo);

    cudaFuncSetAttribute(attn_kernel, cudaFuncAttributeMaxDynamicSharedMemorySize, ATTN_SMEM_BYTES);
    cudaFuncSetAttribute(mma_gemm<0>, cudaFuncAttributeMaxDynamicSharedMemorySize, GEMM_SMEM);
    cudaFuncSetAttribute(mma_gemm<1>, cudaFuncAttributeMaxDynamicSharedMemorySize, GEMM_SMEM);
    cudaFuncSetAttribute(mma_gemm<2>, cudaFuncAttributeMaxDynamicSharedMemorySize, GEMM_SMEM);

    auto SPLIT = [&](const float* src, __nv_bfloat16* h, __nv_bfloat16* l, size_t n) {
        split_kernel<<<(unsigned)((n / 4 + 255) / 256), 256>>>(
            (const float4*)src, (__nv_bfloat162*)h, (__nv_bfloat162*)l, n / 4);
    };

    // Keep launch index 3 (ncu capture) = patch-embed GEMM.
    mean_kernel<<<(BATCH * IMG * IMG + 255) / 256, 256>>>(img);                       // 0
    patches_kernel<<<(unsigned)(((size_t)MPE * PD + 255) / 256), 256>>>(img);         // 1
    SPLIT(patch_w, wph, wpl, (size_t)DIM * PD);                                       // 2
    mma_gemm<0><<<dim3(DIM / 128, MPE / 128), 256, GEMM_SMEM>>>(                      // 3 <- ncu
        a1h, a1l, wph, wpl, patch_b, nullptr, p_emb, nullptr, nullptr, DIM, PD);
    SPLIT(qkv_w,   wqh, wql, (size_t)DEPTH * TRI * DIM);
    SPLIT(out_w,   woh, wol, (size_t)DEPTH * DIM * INNER);
    SPLIT(ff_w1,   w1h, w1l, (size_t)DEPTH * MLPD * DIM);
    SPLIT(ff_w2,   w2h, w2l, (size_t)DEPTH * DIM * MLPD);
    assemble_kernel<<<(unsigned)(((size_t)BATCH * NT * DIM + 255) / 256), 256>>>(cls_tok, pos_emb);

    for (int l = 0; l < DEPTH; l++) {
        const __nv_bfloat16* lqh = wqh + (size_t)l * TRI * DIM;
        const __nv_bfloat16* lql = wql + (size_t)l * TRI * DIM;
        const __nv_bfloat16* loh = woh + (size_t)l * DIM * INNER;
        const __nv_bfloat16* lol = wol + (size_t)l * DIM * INNER;
        const __nv_bfloat16* l1h = w1h + (size_t)l * MLPD * DIM;
        const __nv_bfloat16* l1l = w1l + (size_t)l * MLPD * DIM;
        const __nv_bfloat16* l2h = w2h + (size_t)l * DIM * MLPD;
        const __nv_bfloat16* l2l = w2l + (size_t)l * DIM * MLPD;

        ln_split_kernel<<<MROWS, 96>>>(p_x, ln1_g + (size_t)l * DIM, ln1_b + (size_t)l * DIM, a1h, a1l);
        mma_gemm<0><<<dim3(TRI / 128, MPAD / 128), 256, GEMM_SMEM>>>(
            a1h, a1l, lqh, lql, nullptr, nullptr, p_qkv, nullptr, nullptr, TRI, DIM);
        attn_kernel<<<BATCH * NH, 256, ATTN_SMEM_BYTES>>>(scale, l);
        mma_gemm<2><<<dim3(DIM / 128, MPAD / 128), 256, GEMM_SMEM>>>(
            a2h, a2l, loh, lol, out_b + (size_t)l * DIM, p_x, p_x, nullptr, nullptr, DIM, INNER);
        ln_split_kernel<<<MROWS, 96>>>(p_x, ln2_g + (size_t)l * DIM, ln2_b + (size_t)l * DIM, a1h, a1l);
        mma_gemm<1><<<dim3(MLPD / 128, MPAD / 128), 256, GEMM_SMEM>>>(
            a1h, a1l, l1h, l1l, ff_b1 + (size_t)l * MLPD, nullptr, nullptr, a2h, a2l, MLPD, DIM);
        mma_gemm<2><<<dim3(DIM / 128, MPAD / 128), 256, GEMM_SMEM>>>(
            a2h, a2l, l2h, l2l, ff_b2 + (size_t)l * DIM, p_x, p_x, nullptr, nullptr, DIM, MLPD);
    }

    ln_kernel<<<BATCH, 128>>>(p_x, lnf_g, lnf_b, p_cls, (size_t)NT * DIM);
    head_kernel<<<dim3((NCLS + 255) / 256, BATCH), 256>>>(head_w, head_b, out);
}

// round 12
// speedup vs baseline: 1.2211x; 1.2169x over previous
#include <cuda_runtime.h>
#include <cuda_bf16.h>
#include <math.h>
#include <cstdint>

// ---------------- problem constants ----------------
constexpr int BATCH = 64;
constexpr int IMG   = 224;
constexpr int PCH   = 16;
constexpr int SHIFT = 8;
constexpr int GRD   = 14;
constexpr int NPAT  = 196;
constexpr int NT    = 197;
constexpr int DIM   = 384;
constexpr int DEPTH = 12;
constexpr int NH    = 12;
constexpr int DHD   = 32;
constexpr int INNER = 384;
constexpr int TRI   = 1152;
constexpr int MLPD  = 1536;
constexpr int NCLS  = 1000;
constexpr int PD    = 1792;
constexpr float LNEPS = 1e-5f;

constexpr int MROWS = BATCH * NT;            // 12608
constexpr int MPAD  = 12672;                 // 99 * 128
constexpr int MPE   = BATCH * NPAT;          // 12544 = 98 * 128

// ---------------- attention smem layout ----------------
constexpr int KT_STRIDE = 225;
constexpr int VT_STRIDE = 228;
constexpr int ATTN_KT_FLOATS = DHD * KT_STRIDE;
constexpr int ATTN_VT_FLOATS = DHD * VT_STRIDE;
constexpr int ATTN_PW_FLOATS = 8 * 4 * 224;
constexpr int ATTN_SMEM_BYTES = (ATTN_KT_FLOATS + ATTN_VT_FLOATS + ATTN_PW_FLOATS) * 4;

// ---------------- GEMM tile config ----------------
// Row = 144B: hi 32xbf16 at [0,64), lo at [64,128), 16B pad. ldmatrix phases
// (9r mod 8)=r mod 8 -> conflict-free. Stage = 2 tiles x 18432B = 36864B;
// 3 stages = 110592B -> 2 CTAs/SM.
constexpr int BK      = 32;
constexpr int ROW2    = 144;
constexpr int TILE2   = 128 * ROW2;           // 18432
constexpr int STAGE_B = 2 * TILE2;            // 36864
constexpr int STAGES  = 3;
constexpr int GEMM_SMEM = STAGES * STAGE_B;   // 110592

// ---------------- device scratch ----------------
__device__ float g_mean [BATCH * IMG * IMG];
__device__ float g_emb  [(size_t)MPE * DIM];
__device__ float g_x    [(size_t)MPAD * DIM];
__device__ float g_qkv  [(size_t)MPAD * TRI];
__device__ float g_cls  [BATCH * DIM];

__device__ __align__(16) __nv_bfloat16 g_act1_hi[(size_t)MPE * PD];
__device__ __align__(16) __nv_bfloat16 g_act1_lo[(size_t)MPE * PD];
__device__ __align__(16) __nv_bfloat16 g_act2_hi[(size_t)MPAD * MLPD];
__device__ __align__(16) __nv_bfloat16 g_act2_lo[(size_t)MPAD * MLPD];

__device__ __align__(16) __nv_bfloat16 g_wp_hi  [DIM * PD];
__device__ __align__(16) __nv_bfloat16 g_wp_lo  [DIM * PD];
__device__ __align__(16) __nv_bfloat16 g_wqkv_hi[(size_t)DEPTH * TRI * DIM];
__device__ __align__(16) __nv_bfloat16 g_wqkv_lo[(size_t)DEPTH * TRI * DIM];
__device__ __align__(16) __nv_bfloat16 g_wout_hi[(size_t)DEPTH * DIM * INNER];
__device__ __align__(16) __nv_bfloat16 g_wout_lo[(size_t)DEPTH * DIM * INNER];
__device__ __align__(16) __nv_bfloat16 g_wf1_hi [(size_t)DEPTH * MLPD * DIM];
__device__ __align__(16) __nv_bfloat16 g_wf1_lo [(size_t)DEPTH * MLPD * DIM];
__device__ __align__(16) __nv_bfloat16 g_wf2_hi [(size_t)DEPTH * DIM * MLPD];
__device__ __align__(16) __nv_bfloat16 g_wf2_lo [(size_t)DEPTH * DIM * MLPD];

// ---------------- helpers ----------------
__device__ __forceinline__ uint32_t smem_u32(const void* p) {
    uint32_t a;
    asm("{ .reg .u64 t; cvta.to.shared.u64 t, %1; cvt.u32.u64 %0, t; }" : "=r"(a) : "l"(p));
    return a;
}
__device__ __forceinline__ void cp_async16(uint32_t dst, const void* src) {
    asm volatile("cp.async.cg.shared.global [%0], [%1], 16;" :: "r"(dst), "l"(src));
}
__device__ __forceinline__ void cp_commit() {
    asm volatile("cp.async.commit_group;" ::: "memory");
}
template <int N>
__device__ __forceinline__ void cp_wait() {
    asm volatile("cp.async.wait_group %0;" :: "n"(N) : "memory");
}
__device__ __forceinline__ void ldsm4(uint32_t* r, uint32_t a) {
    asm volatile("ldmatrix.sync.aligned.m8n8.x4.shared.b16 {%0,%1,%2,%3}, [%4];"
        : "=r"(r[0]), "=r"(r[1]), "=r"(r[2]), "=r"(r[3]) : "r"(a));
}
__device__ __forceinline__ void mma_bf16(float* c, const uint32_t* a, const uint32_t* b) {
    asm volatile(
        "mma.sync.aligned.m16n8k16.row.col.f32.bf16.bf16.f32 "
        "{%0,%1,%2,%3},{%4,%5,%6,%7},{%8,%9},{%0,%1,%2,%3};"
        : "+f"(c[0]), "+f"(c[1]), "+f"(c[2]), "+f"(c[3])
        : "r"(a[0]), "r"(a[1]), "r"(a[2]), "r"(a[3]), "r"(b[0]), "r"(b[1]));
}
__device__ __forceinline__ void split_val(float v, __nv_bfloat16& h, __nv_bfloat16& l) {
    h = __float2bfloat16(v);
    l = __float2bfloat16(v - __bfloat162float(h));
}

// ---------------- split weights (vectorized x4) ----------------
__global__ void split_kernel(const float4* __restrict__ in,
                             __nv_bfloat162* __restrict__ hi,
                             __nv_bfloat162* __restrict__ lo, size_t n4) {
    size_t i = (size_t)blockIdx.x * blockDim.x + threadIdx.x;
    if (i >= n4) return;
    float4 v = in[i];
    __nv_bfloat16 hx, lx, hy, ly, hz, lz, hw, lw;
    split_val(v.x, hx, lx); split_val(v.y, hy, ly);
    split_val(v.z, hz, lz); split_val(v.w, hw, lw);
    hi[2*i]   = __nv_bfloat162(hx, hy);
    hi[2*i+1] = __nv_bfloat162(hz, hw);
    lo[2*i]   = __nv_bfloat162(lx, ly);
    lo[2*i+1] = __nv_bfloat162(lz, lw);
}

// ---------------- channel-mean image ----------------
__global__ void mean_kernel(const float* __restrict__ img) {
    int idx = blockIdx.x * blockDim.x + threadIdx.x;
    if (idx >= BATCH * IMG * IMG) return;
    int b = idx / (IMG * IMG);
    int hw = idx % (IMG * IMG);
    const float* p = img + (size_t)b * 3 * IMG * IMG + hw;
    g_mean[idx] = (p[0] + p[(size_t)IMG*IMG] + p[(size_t)2*IMG*IMG]) * (1.0f / 3.0f);
}

// ---------------- patch extraction -> split bf16 ----------------
__global__ void patches_kernel(const float* __restrict__ img) {
    size_t idx = (size_t)blockIdx.x * blockDim.x + threadIdx.x;
    if (idx >= (size_t)MPE * PD) return;
    int pd = (int)(idx % PD);
    int n  = (int)((idx / PD) % NPAT);
    int b  = (int)(idx / ((size_t)PD * NPAT));
    int ch = pd % 7;
    int pp = pd / 7;
    int pr = pp / PCH, pc = pp % PCH;
    int gr = n / GRD,  gc = n % GRD;
    int hh = gr * PCH + pr;
    int ww = gc * PCH + pc;
    float v;
    if (ch < 3) {
        v = img[(((size_t)b * 3 + ch) * IMG + hh) * IMG + ww];
    } else {
        int sh = hh, sw = ww;
        if (ch == 3) sw = ww - SHIFT;
        else if (ch == 4) sw = ww + SHIFT;
        else if (ch == 5) sh = hh - SHIFT;
        else              sh = hh + SHIFT;
        if (sh < 0 || sh >= IMG || sw < 0 || sw >= IMG) v = 0.0f;
        else v = g_mean[((size_t)b * IMG + sh) * IMG + sw];
    }
    split_val(v, g_act1_hi[idx], g_act1_lo[idx]);
}

// ---------------- HMMA split-bf16 GEMM ----------------
// 128x128 CTA tile, BK=32, 8 warps, 3-stage pipeline (load-at-top), one
// barrier per chunk, 2 CTAs/SM. Loader uses round-8 coalesced mapping:
// per cp.async instruction a warp covers 8 rows x 4 consecutive 16B chunks
// of ONE source array (8 x 64B contiguous runs).
template <int EPI>
__global__ __launch_bounds__(256, 2)
void mma_gemm(const __nv_bfloat16* __restrict__ Ahi, const __nv_bfloat16* __restrict__ Alo,
              const __nv_bfloat16* __restrict__ Whi, const __nv_bfloat16* __restrict__ Wlo,
              const float* __restrict__ bias, const float* __restrict__ res,
              float* __restrict__ C, __nv_bfloat16* __restrict__ Chi,
              __nv_bfloat16* __restrict__ Clo, int N, int K) {
    extern __shared__ char sm[];
    uint32_t sbase = smem_u32(sm);
    int tid = threadIdx.x, wid = tid >> 5, lane = tid & 31;
    int wm = wid & 3, wn = wid >> 2;
    int m0 = blockIdx.y * 128, n0 = blockIdx.x * 128;

    const __nv_bfloat16* ah = Ahi + (size_t)m0 * K;
    const __nv_bfloat16* al = Alo + (size_t)m0 * K;
    const __nv_bfloat16* wh = Whi + (size_t)n0 * K;
    const __nv_bfloat16* wl = Wlo + (size_t)n0 * K;
    int nch = K / BK;

    float acc[2][8][4];
#pragma unroll
    for (int i = 0; i < 2; i++)
#pragma unroll
        for (int j = 0; j < 8; j++)
#pragma unroll
            for (int q = 0; q < 4; q++) acc[i][j][q] = 0.0f;

    // round-8 style loader mapping: row = tid>>2 (+64), chunk j = tid&3.
    int c_row0 = tid >> 2, c_j = tid & 3;
    int c_row1 = c_row0 + 64;
    size_t g_off0 = (size_t)c_row0 * K + c_j * 8;
    size_t g_off1 = (size_t)c_row1 * K + c_j * 8;
    uint32_t s_off0 = c_row0 * ROW2 + c_j * 16;
    uint32_t s_off1 = c_row1 * ROW2 + c_j * 16;

    auto load_st = [&](int st, int c) {
        uint32_t dstb = sbase + st * STAGE_B;
        int ko = c * BK;
        // A-hi -> [0,64), A-lo -> [64,128) of bufA rows; W same in bufW.
        cp_async16(dstb + s_off0,              ah + g_off0 + ko);
        cp_async16(dstb + s_off1,              ah + g_off1 + ko);
        cp_async16(dstb + s_off0 + 64,         al + g_off0 + ko);
        cp_async16(dstb + s_off1 + 64,         al + g_off1 + ko);
        cp_async16(dstb + TILE2 + s_off0,      wh + g_off0 + ko);
        cp_async16(dstb + TILE2 + s_off1,      wh + g_off1 + ko);
        cp_async16(dstb + TILE2 + s_off0 + 64, wl + g_off0 + ko);
        cp_async16(dstb + TILE2 + s_off1 + 64, wl + g_off1 + ko);
        cp_commit();
    };

    // fragment address bases (byte col within row: hi at kk*32+a_cb, lo +64)
    int a_r  = (lane & 15);
    int a_cb = (lane >> 4) * 16;
    int w_r  = ((lane >> 4) << 3) + (lane & 7);
    int w_cb = ((lane >> 3) & 1) * 16;

    load_st(0, 0);
    if (nch > 1) load_st(1, 1); else cp_commit();

    for (int c = 0; c < nch; c++) {
        cp_wait<1>();
        __syncthreads();
        // load chunk c+2 into slot (c+2)%3 (held c-1, done by all warps).
        if (c + 2 < nch) load_st((c + 2) % 3, c + 2);
        else cp_commit();

        uint32_t ab = sbase + (c % 3) * STAGE_B;
        uint32_t bb = ab + TILE2;
#pragma unroll
        for (int kk = 0; kk < 2; kk++) {
            uint32_t ahr[2][4], alr[2][4];
#pragma unroll
            for (int mt = 0; mt < 2; mt++) {
                uint32_t addr = ab + (wm * 32 + mt * 16 + a_r) * ROW2 + kk * 32 + a_cb;
                ldsm4(ahr[mt], addr);
                ldsm4(alr[mt], addr + 64);
            }
#pragma unroll
            for (int ng = 0; ng < 4; ng++) {
                uint32_t addr = bb + (wn * 64 + ng * 16 + w_r) * ROW2 + kk * 32 + w_cb;
                uint32_t rh[4], rl[4];
                ldsm4(rh, addr);
                ldsm4(rl, addr + 64);
#pragma unroll
                for (int half = 0; half < 2; half++) {
                    int nt = ng * 2 + half;
                    uint32_t bh[2] = { rh[half*2], rh[half*2+1] };
                    uint32_t bl[2] = { rl[half*2], rl[half*2+1] };
#pragma unroll
                    for (int mt = 0; mt < 2; mt++) {
                        mma_bf16(acc[mt][nt], ahr[mt], bh);
                        mma_bf16(acc[mt][nt], ahr[mt], bl);
                        mma_bf16(acc[mt][nt], alr[mt], bh);
                    }
                }
            }
        }
    }

    int gid = lane >> 2;
    int cpr = (lane & 3) * 2;
#pragma unroll
    for (int mt = 0; mt < 2; mt++) {
        int r0 = m0 + wm * 32 + mt * 16 + gid;
        int r1 = r0 + 8;
#pragma unroll
        for (int nt = 0; nt < 8; nt++) {
            int n = n0 + wn * 64 + nt * 8 + cpr;
            float b0 = bias ? bias[n] : 0.0f;
            float b1 = bias ? bias[n + 1] : 0.0f;
            float v00 = acc[mt][nt][0] + b0, v01 = acc[mt][nt][1] + b1;
            float v10 = acc[mt][nt][2] + b0, v11 = acc[mt][nt][3] + b1;
            size_t o0 = (size_t)r0 * N + n;
            size_t o1 = (size_t)r1 * N + n;
            if (EPI == 1) {
                v00 = 0.5f * v00 * (1.0f + erff(v00 * 0.70710678118654752f));
                v01 = 0.5f * v01 * (1.0f + erff(v01 * 0.70710678118654752f));
                v10 = 0.5f * v10 * (1.0f + erff(v10 * 0.70710678118654752f));
                v11 = 0.5f * v11 * (1.0f + erff(v11 * 0.70710678118654752f));
                split_val(v00, Chi[o0], Clo[o0]);
                split_val(v01, Chi[o0 + 1], Clo[o0 + 1]);
                split_val(v10, Chi[o1], Clo[o1]);
                split_val(v11, Chi[o1 + 1], Clo[o1 + 1]);
            } else if (EPI == 2) {
                float2 r0v = *(const float2*)(res + o0);
                float2 r1v = *(const float2*)(res + o1);
                *(float2*)(C + o0) = make_float2(v00 + r0v.x, v01 + r0v.y);
                *(float2*)(C + o1) = make_float2(v10 + r1v.x, v11 + r1v.y);
            } else {
                *(float2*)(C + o0) = make_float2(v00, v01);
                *(float2*)(C + o1) = make_float2(v10, v11);
            }
        }
    }
}

// ---------------- assemble tokens ----------------
__global__ void assemble_kernel(const float* __restrict__ cls_tok,
                                const float* __restrict__ pos) {
    size_t idx = (size_t)blockIdx.x * blockDim.x + threadIdx.x;
    if (idx >= (size_t)BATCH * NT * DIM) return;
    int d = (int)(idx % DIM);
    int n = (int)((idx / DIM) % NT);
    int b = (int)(idx / ((size_t)DIM * NT));
    float v = (n == 0) ? cls_tok[d] : g_emb[((size_t)b * NPAT + (n - 1)) * DIM + d];
    g_x[idx] = v + pos[(size_t)n * DIM + d];
}

// ---------------- layernorm -> split bf16 (96 threads, float4) ----------------
__global__ void ln_split_kernel(const float* __restrict__ in, const float* __restrict__ g,
                                const float* __restrict__ be,
                                __nv_bfloat16* __restrict__ hi,
                                __nv_bfloat16* __restrict__ lo) {
    __shared__ float sh1[3], sh2[3];
    int row = blockIdx.x, tid = threadIdx.x;        // 96 threads
    int wrp = tid >> 5, lane = tid & 31;
    float4 v = ((const float4*)(in + (size_t)row * DIM))[tid];
    float s = v.x + v.y + v.z + v.w;
#pragma unroll
    for (int o = 16; o; o >>= 1) s += __shfl_xor_sync(0xFFFFFFFFu, s, o);
    if (lane == 0) sh1[wrp] = s;
    __syncthreads();
    float mu = (sh1[0] + sh1[1] + sh1[2]) * (1.0f / DIM);
    float dx = v.x - mu, dy = v.y - mu, dz = v.z - mu, dw = v.w - mu;
    float var = dx*dx + dy*dy + dz*dz + dw*dw;
#pragma unroll
    for (int o = 16; o; o >>= 1) var += __shfl_xor_sync(0xFFFFFFFFu, var, o);
    if (lane == 0) sh2[wrp] = var;
    __syncthreads();
    float rstd = rsqrtf((sh2[0] + sh2[1] + sh2[2]) * (1.0f / DIM) + LNEPS);
    float4 gv = ((const float4*)g)[tid];
    float4 bv = ((const float4*)be)[tid];
    float y0 = dx * rstd * gv.x + bv.x;
    float y1 = dy * rstd * gv.y + bv.y;
    float y2 = dz * rstd * gv.z + bv.z;
    float y3 = dw * rstd * gv.w + bv.w;
    __nv_bfloat16 h0,l0,h1,l1,h2,l2,h3,l3;
    split_val(y0,h0,l0); split_val(y1,h1,l1); split_val(y2,h2,l2); split_val(y3,h3,l3);
    __nv_bfloat162 hp[2] = { __nv_bfloat162(h0,h1), __nv_bfloat162(h2,h3) };
    __nv_bfloat162 lp[2] = { __nv_bfloat162(l0,l1), __nv_bfloat162(l2,l3) };
    ((uint2*)(hi + (size_t)row * DIM))[tid] = *(uint2*)hp;
    ((uint2*)(lo + (size_t)row * DIM))[tid] = *(uint2*)lp;
}

// ---------------- layernorm fp32 (final, strided input) ----------------
__global__ void ln_kernel(const float* __restrict__ in, const float* __restrict__ g,
                          const float* __restrict__ be, float* __restrict__ out,
                          size_t in_stride) {
    __shared__ float sh1[4], sh2[4];
    int row = blockIdx.x, tid = threadIdx.x;
    const float* x = in + (size_t)row * in_stride;
    float v0 = x[tid], v1 = x[tid + 128], v2 = x[tid + 256];
    float s = v0 + v1 + v2;
#pragma unroll
    for (int o = 16; o; o >>= 1) s += __shfl_xor_sync(0xFFFFFFFFu, s, o);
    if ((tid & 31) == 0) sh1[tid >> 5] = s;
    __syncthreads();
    float mu = (sh1[0] + sh1[1] + sh1[2] + sh1[3]) * (1.0f / DIM);
    float d0 = v0 - mu, d1 = v1 - mu, d2 = v2 - mu;
    float var = d0*d0 + d1*d1 + d2*d2;
#pragma unroll
    for (int o = 16; o; o >>= 1) var += __shfl_xor_sync(0xFFFFFFFFu, var, o);
    if ((tid & 31) == 0) sh2[tid >> 5] = var;
    __syncthreads();
    float rstd = rsqrtf((sh2[0] + sh2[1] + sh2[2] + sh2[3]) * (1.0f / DIM) + LNEPS);
    float* y = out + (size_t)row * DIM;
    y[tid]       = d0 * rstd * g[tid]       + be[tid];
    y[tid + 128] = d1 * rstd * g[tid + 128] + be[tid + 128];
    y[tid + 256] = d2 * rstd * g[tid + 256] + be[tid + 256];
}

// ---------------- attention: one block per (b,h), warp-autonomous rows ----------------
__global__ __launch_bounds__(256, 2)
void attn_kernel(const float* __restrict__ scale, int layer) {
    extern __shared__ float smf[];
    float* kT = smf;
    float* vT = kT + ATTN_KT_FLOATS;
    float* pw = vT + ATTN_VT_FLOATS;

    int bh = blockIdx.x;
    int b = bh / NH, hd = bh % NH;
    int tid = threadIdx.x, wid = tid >> 5, lane = tid & 31;
    float sc = scale[layer * NH + hd];
    const float* base = g_qkv + (size_t)b * NT * TRI;

    for (int t = tid; t < NT * DHD; t += 256) {
        int n = t >> 5, d = t & 31;
        kT[d * KT_STRIDE + n] = base[(size_t)n * TRI +     INNER + hd * DHD + d];
        vT[d * VT_STRIDE + n] = base[(size_t)n * TRI + 2 * INNER + hd * DHD + d];
    }
    for (int t = tid; t < DHD * (VT_STRIDE - NT); t += 256) {
        int d = t / (VT_STRIDE - NT), n = NT + t % (VT_STRIDE - NT);
        vT[d * VT_STRIDE + n] = 0.0f;
    }
    __syncthreads();

    float* pr = pw + wid * 4 * 224;

    for (int base_row = wid * 4; base_row < NT; base_row += 32) {
        float q0, q1, q2, q3;
        {
            int i0 = base_row, i1 = base_row + 1, i2 = base_row + 2, i3 = base_row + 3;
            q0 = (i0 < NT) ? base[(size_t)i0 * TRI + hd * DHD + lane] : 0.0f;
            q1 = (i1 < NT) ? base[(size_t)i1 * TRI + hd * DHD + lane] : 0.0f;
            q2 = (i2 < NT) ? base[(size_t)i2 * TRI + hd * DHD + lane] : 0.0f;
            q3 = (i3 < NT) ? base[(size_t)i3 * TRI + hd * DHD + lane] : 0.0f;
        }
        float s[4][7];
#pragma unroll
        for (int r = 0; r < 4; r++)
#pragma unroll
            for (int t = 0; t < 7; t++) s[r][t] = 0.0f;

#pragma unroll
        for (int d = 0; d < 32; d++) {
            float a0 = __shfl_sync(0xFFFFFFFFu, q0, d);
            float a1 = __shfl_sync(0xFFFFFFFFu, q1, d);
            float a2 = __shfl_sync(0xFFFFFFFFu, q2, d);
            float a3 = __shfl_sync(0xFFFFFFFFu, q3, d);
            const float* krow = kT + d * KT_STRIDE + lane;
#pragma unroll
            for (int t = 0; t < 7; t++) {
                float kv = krow[32 * t];
                s[0][t] = fmaf(a0, kv, s[0][t]);
                s[1][t] = fmaf(a1, kv, s[1][t]);
                s[2][t] = fmaf(a2, kv, s[2][t]);
                s[3][t] = fmaf(a3, kv, s[3][t]);
            }
        }

#pragma unroll
        for (int r = 0; r < 4; r++) {
            int i = base_row + r;
            float mx = -INFINITY;
#pragma unroll
            for (int t = 0; t < 7; t++) {
                int j = lane + 32 * t;
                if (j >= NT || j == i) s[r][t] = -INFINITY;
                mx = fmaxf(mx, s[r][t]);
            }
#pragma unroll
            for (int o = 16; o; o >>= 1) mx = fmaxf(mx, __shfl_xor_sync(0xFFFFFFFFu, mx, o));
            float su = 0.0f;
#pragma unroll
            for (int t = 0; t < 7; t++) {
                float p = __expf((s[r][t] - mx) * sc);
                s[r][t] = p;
                su += p;
            }
#pragma unroll
            for (int o = 16; o; o >>= 1) su += __shfl_xor_sync(0xFFFFFFFFu, su, o);
            float inv = 1.0f / su;
#pragma unroll
            for (int t = 0; t < 7; t++)
                pr[r * 224 + lane + 32 * t] = s[r][t] * inv;
        }
        __syncwarp();

        float c0 = 0.0f, c1 = 0.0f, c2 = 0.0f, c3 = 0.0f;
        const float* vrow = vT + lane * VT_STRIDE;
        for (int jj = 0; jj < 200; jj += 4) {
            float4 vv = *(const float4*)(vrow + jj);
            float4 p0 = *(const float4*)(pr + 0 * 224 + jj);
            float4 p1 = *(const float4*)(pr + 1 * 224 + jj);
            float4 p2 = *(const float4*)(pr + 2 * 224 + jj);
            float4 p3 = *(const float4*)(pr + 3 * 224 + jj);
            c0 += p0.x*vv.x + p0.y*vv.y + p0.z*vv.z + p0.w*vv.w;
            c1 += p1.x*vv.x + p1.y*vv.y + p1.z*vv.z + p1.w*vv.w;
            c2 += p2.x*vv.x + p2.y*vv.y + p2.z*vv.z + p2.w*vv.w;
            c3 += p3.x*vv.x + p3.y*vv.y + p3.z*vv.z + p3.w*vv.w;
        }
        float accs[4] = {c0, c1, c2, c3};
#pragma unroll
        for (int r = 0; r < 4; r++) {
            int i = base_row + r;
            if (i < NT) {
                size_t o = ((size_t)b * NT + i) * INNER + hd * DHD + lane;
                split_val(accs[r], g_act2_hi[o], g_act2_lo[o]);
            }
        }
        __syncwarp();
    }
}

// ---------------- classifier head ----------------
__global__ void head_kernel(const float* __restrict__ w, const float* __restrict__ bias,
                            float* __restrict__ out) {
    int b = blockIdx.y;
    int n = blockIdx.x * blockDim.x + threadIdx.x;
    if (n >= NCLS) return;
    const float* xr = g_cls + (size_t)b * DIM;
    const float* wr = w + (size_t)n * DIM;
    float acc = 0.0f;
    for (int k = 0; k < DIM; k++) acc += xr[k] * wr[k];
    out[(size_t)b * NCLS + n] = acc + bias[n];
}

// ---------------- host launch ----------------
extern "C" void kernel_launch(void* const* d_in, const int* in_sizes, int n_in,
                              void* d_out, int out_size) {
    const float* img     = (const float*)d_in[0];
    const float* patch_w = (const float*)d_in[1];
    const float* patch_b = (const float*)d_in[2];
    const float* pos_emb = (const float*)d_in[3];
    const float* cls_tok = (const float*)d_in[4];
    const float* ln1_g   = (const float*)d_in[5];
    const float* ln1_b   = (const float*)d_in[6];
    const float* qkv_w   = (const float*)d_in[7];
    const float* scale   = (const float*)d_in[8];
    const float* out_w   = (const float*)d_in[9];
    const float* out_b   = (const float*)d_in[10];
    const float* ln2_g   = (const float*)d_in[11];
    const float* ln2_b   = (const float*)d_in[12];
    const float* ff_w1   = (const float*)d_in[13];
    const float* ff_b1   = (const float*)d_in[14];
    const float* ff_w2   = (const float*)d_in[15];
    const float* ff_b2   = (const float*)d_in[16];
    const float* lnf_g   = (const float*)d_in[17];
    const float* lnf_b   = (const float*)d_in[18];
    const float* head_w  = (const float*)d_in[19];
    const float* head_b  = (const float*)d_in[20];
    float* out = (float*)d_out;

    float *p_emb, *p_x, *p_qkv, *p_cls;
    __nv_bfloat16 *a1h, *a1l, *a2h, *a2l;
    __nv_bfloat16 *wph, *wpl, *wqh, *wql, *woh, *wol, *w1h, *w1l, *w2h, *w2l;
    cudaGetSymbolAddress((void**)&p_emb, g_emb);
    cudaGetSymbolAddress((void**)&p_x,   g_x);
    cudaGetSymbolAddress((void**)&p_qkv, g_qkv);
    cudaGetSymbolAddress((void**)&p_cls, g_cls);
    cudaGetSymbolAddress((void**)&a1h, g_act1_hi);
    cudaGetSymbolAddress((void**)&a1l, g_act1_lo);
    cudaGetSymbolAddress((void**)&a2h, g_act2_hi);
    cudaGetSymbolAddress((void**)&a2l, g_act2_lo);
    cudaGetSymbolAddress((void**)&wph, g_wp_hi);
    cudaGetSymbolAddress((void**)&wpl, g_wp_lo);
    cudaGetSymbolAddress((void**)&wqh, g_wqkv_hi);
    cudaGetSymbolAddress((void**)&wql, g_wqkv_lo);
    cudaGetSymbolAddress((void**)&woh, g_wout_hi);
    cudaGetSymbolAddress((void**)&wol, g_wout_lo);
    cudaGetSymbolAddress((void**)&w1h, g_wf1_hi);
    cudaGetSymbolAddress((void**)&w1l, g_wf1_lo);
    cudaGetSymbolAddress((void**)&w2h, g_wf2_hi);
    cudaGetSymbolAddress((void**)&w2l, g_wf2_lo);

    cudaFuncSetAttribute(attn_kernel, cudaFuncAttributeMaxDynamicSharedMemorySize, ATTN_SMEM_BYTES);
    cudaFuncSetAttribute(mma_gemm<0>, cudaFuncAttributeMaxDynamicSharedMemorySize, GEMM_SMEM);
    cudaFuncSetAttribute(mma_gemm<1>, cudaFuncAttributeMaxDynamicSharedMemorySize, GEMM_SMEM);
    cudaFuncSetAttribute(mma_gemm<2>, cudaFuncAttributeMaxDynamicSharedMemorySize, GEMM_SMEM);

    auto SPLIT = [&](const float* src, __nv_bfloat16* h, __nv_bfloat16* l, size_t n) {
        split_kernel<<<(unsigned)((n / 4 + 255) / 256), 256>>>(
            (const float4*)src, (__nv_bfloat162*)h, (__nv_bfloat162*)l, n / 4);
    };

    // Keep launch index 3 (ncu capture) = patch-embed GEMM.
    mean_kernel<<<(BATCH * IMG * IMG + 255) / 256, 256>>>(img);                       // 0
    patches_kernel<<<(unsigned)(((size_t)MPE * PD + 255) / 256), 256>>>(img);         // 1
    SPLIT(patch_w, wph, wpl, (size_t)DIM * PD);                                       // 2
    mma_gemm<0><<<dim3(DIM / 128, MPE / 128), 256, GEMM_SMEM>>>(                      // 3 <- ncu
        a1h, a1l, wph, wpl, patch_b, nullptr, p_emb, nullptr, nullptr, DIM, PD);
    SPLIT(qkv_w,   wqh, wql, (size_t)DEPTH * TRI * DIM);
    SPLIT(out_w,   woh, wol, (size_t)DEPTH * DIM * INNER);
    SPLIT(ff_w1,   w1h, w1l, (size_t)DEPTH * MLPD * DIM);
    SPLIT(ff_w2,   w2h, w2l, (size_t)DEPTH * DIM * MLPD);
    assemble_kernel<<<(unsigned)(((size_t)BATCH * NT * DIM + 255) / 256), 256>>>(cls_tok, pos_emb);

    for (int l = 0; l < DEPTH; l++) {
        const __nv_bfloat16* lqh = wqh + (size_t)l * TRI * DIM;
        const __nv_bfloat16* lql = wql + (size_t)l * TRI * DIM;
        const __nv_bfloat16* loh = woh + (size_t)l * DIM * INNER;
        const __nv_bfloat16* lol = wol + (size_t)l * DIM * INNER;
        const __nv_bfloat16* l1h = w1h + (size_t)l * MLPD * DIM;
        const __nv_bfloat16* l1l = w1l + (size_t)l * MLPD * DIM;
        const __nv_bfloat16* l2h = w2h + (size_t)l * DIM * MLPD;
        const __nv_bfloat16* l2l = w2l + (size_t)l * DIM * MLPD;

        ln_split_kernel<<<MROWS, 96>>>(p_x, ln1_g + (size_t)l * DIM, ln1_b + (size_t)l * DIM, a1h, a1l);
        mma_gemm<0><<<dim3(TRI / 128, MPAD / 128), 256, GEMM_SMEM>>>(
            a1h, a1l, lqh, lql, nullptr, nullptr, p_qkv, nullptr, nullptr, TRI, DIM);
        attn_kernel<<<BATCH * NH, 256, ATTN_SMEM_BYTES>>>(scale, l);
        mma_gemm<2><<<dim3(DIM / 128, MPAD / 128), 256, GEMM_SMEM>>>(
            a2h, a2l, loh, lol, out_b + (size_t)l * DIM, p_x, p_x, nullptr, nullptr, DIM, INNER);
        ln_split_kernel<<<MROWS, 96>>>(p_x, ln2_g + (size_t)l * DIM, ln2_b + (size_t)l * DIM, a1h, a1l);
        mma_gemm<1><<<dim3(MLPD / 128, MPAD / 128), 256, GEMM_SMEM>>>(
            a1h, a1l, l1h, l1l, ff_b1 + (size_t)l * MLPD, nullptr, nullptr, a2h, a2l, MLPD, DIM);
        mma_gemm<2><<<dim3(DIM / 128, MPAD / 128), 256, GEMM_SMEM>>>(
            a2h, a2l, l2h, l2l, ff_b2 + (size_t)l * DIM, p_x, p_x, nullptr, nullptr, DIM, MLPD);
    }

    ln_kernel<<<BATCH, 128>>>(p_x, lnf_g, lnf_b, p_cls, (size_t)NT * DIM);
    head_kernel<<<dim3((NCLS + 255) / 256, BATCH), 256>>>(head_w, head_b, out);
}